// round 16
// baseline (speedup 1.0000x reference)
#include <cuda_runtime.h>
#include <cuda_bf16.h>
#include <cstdint>
#include <math.h>

// ---------------- static config ----------------
#define CDIM   96
#define NHEAD  4
#define HDIM   24
#define NTOK   343
#define NWINS  256
#define LTOT   21952
#define MTOT   87808
#define HIDDEN 384
#define QSCALE_L2E 0.29448890f
#define LOG2E 1.4426950408889634f

// ---------------- scratch (device globals; referenced ONLY in device code) ----
__device__ __nv_bfloat16 g_xw [MTOT*CDIM];
__device__ __nv_bfloat16 g_q  [NWINS*NHEAD*NTOK*HDIM];
__device__ __nv_bfloat16 g_k  [NWINS*NHEAD*NTOK*HDIM];
__device__ __nv_bfloat16 g_v  [NWINS*NHEAD*NTOK*HDIM];
__device__ __nv_bfloat16 g_ao [MTOT*CDIM];
__device__ float         g_x2 [MTOT*CDIM];
__device__ __nv_bfloat16 g_xn2[MTOT*CDIM];
__device__ __nv_bfloat16 g_hbf[MTOT*HIDDEN];
__device__ __nv_bfloat16 g_wq[288*96];
__device__ __nv_bfloat16 g_wp[96*96];
__device__ __nv_bfloat16 g_w1[384*96];
__device__ __nv_bfloat16 g_w2[96*384];
#define BSTR 352
__device__ __nv_bfloat16 g_bias[8*NHEAD*NTOK*BSTR];

// windowed token index -> (batch, spatial l) applying shift (+3 mod 28)
__device__ __forceinline__ int win_to_l(int m, int& bidx) {
    int win = m / NTOK, t = m - win * NTOK;
    bidx = win >> 6; int w3 = win & 63;
    int wh = w3 >> 4, ww = (w3 >> 2) & 3, wd = w3 & 3;
    int a = t / 49, rr = t - a * 49, bb = rr / 7, cc = rr - bb * 7;
    int gh = wh * 7 + a  + 3; if (gh >= 28) gh -= 28;
    int gw = ww * 7 + bb + 3; if (gw >= 28) gw -= 28;
    int gd = wd * 7 + cc + 3; if (gd >= 28) gd -= 28;
    return (gh * 28 + gw) * 28 + gd;
}

// ---------------- merged prep: bias + weights ----------------
__device__ __forceinline__ int seg_grp(int cls_bit, int a) {
    return cls_bit ? (1 + (a >= 4)) : 0;
}

#define PREP_BIAS_BLOCKS (8*NHEAD*NTOK)

__global__ __launch_bounds__(BSTR)
void prep_all(const float* __restrict__ rpb_table,
              const float* __restrict__ qkvw, const float* __restrict__ pw,
              const float* __restrict__ f1w,  const float* __restrict__ f2w)
{
    if (blockIdx.x < PREP_BIAS_BLOCKS) {
        const int bid = blockIdx.x;
        const int i   = bid % NTOK;
        const int t   = bid / NTOK;
        const int h   = t & 3;
        const int cls = t >> 2;
        const int j   = threadIdx.x;

        float val;
        if (j >= NTOK) {
            val = -100.0f;
        } else {
            int ai = i / 49, ri = i - ai * 49, bi = ri / 7, ci = ri - bi * 7;
            int aj = j / 49, rj = j - aj * 49, bj = rj / 7, cj = rj - bj * 7;
            int ridx = 13 * ((ai - aj) + (bi - bj)) + (ci - cj) + 162;
            val = rpb_table[ridx * NHEAD + h];
            int gi = seg_grp((cls >> 2) & 1, ai) * 9 + seg_grp((cls >> 1) & 1, bi) * 3 + seg_grp(cls & 1, ci);
            int gj = seg_grp((cls >> 2) & 1, aj) * 9 + seg_grp((cls >> 1) & 1, bj) * 3 + seg_grp(cls & 1, cj);
            if (gi != gj) val -= 100.0f;
        }
        g_bias[(size_t)bid * BSTR + j] = __float2bfloat16(val * LOG2E);
    } else {
        int i = (blockIdx.x - PREP_BIAS_BLOCKS) * BSTR + threadIdx.x;
        if (i < 288*96) { int n = i / 96,  k = i - n*96;  g_wq[i] = __float2bfloat16(qkvw[k*288 + n]); }
        if (i < 96*96)  { int n = i / 96,  k = i - n*96;  g_wp[i] = __float2bfloat16(pw  [k*96  + n]); }
        if (i < 384*96) { int n = i / 96,  k = i - n*96;  g_w1[i] = __float2bfloat16(f1w [k*384 + n]); }
        if (i < 96*384) { int n = i / 384, k = i - n*384; g_w2[i] = __float2bfloat16(f2w [k*96  + n]); }
    }
}

// ---------------- LayerNorm 1 (warp per token) ----------------
__global__ __launch_bounds__(256)
void ln1_kernel(const float* __restrict__ xin, const float* __restrict__ w,
                const float* __restrict__ b)
{
    int m = blockIdx.x * 8 + (threadIdx.x >> 5);
    int lane = threadIdx.x & 31;
    int bidx; int l = win_to_l(m, bidx);
    const float* src = xin + ((size_t)bidx * LTOT + l) * CDIM;
    __nv_bfloat16* dst = g_xw + (size_t)m * CDIM;
    float v0 = src[lane], v1 = src[lane + 32], v2 = src[lane + 64];
    float s  = v0 + v1 + v2;
    float s2 = v0 * v0 + v1 * v1 + v2 * v2;
    #pragma unroll
    for (int o = 16; o; o >>= 1) {
        s  += __shfl_xor_sync(0xffffffffu, s,  o);
        s2 += __shfl_xor_sync(0xffffffffu, s2, o);
    }
    float mu  = s * (1.0f / 96.0f);
    float var = s2 * (1.0f / 96.0f) - mu * mu;
    float rs  = rsqrtf(var + 1e-5f);
    dst[lane]      = __float2bfloat16((v0 - mu) * rs * w[lane]      + b[lane]);
    dst[lane + 32] = __float2bfloat16((v1 - mu) * rs * w[lane + 32] + b[lane + 32]);
    dst[lane + 64] = __float2bfloat16((v2 - mu) * rs * w[lane + 64] + b[lane + 64]);
}

// ---------------- bf16 HMMA GEMM (m16n8k16) with fused epilogues ----------------
enum { EPI_QKV = 0, EPI_PROJ = 1, EPI_GELU = 2, EPI_FC2 = 3 };
#define ASTR 104

__device__ __forceinline__ float gelu_exact(float x) {
    return 0.5f * x * (1.0f + erff(x * 0.70710678118654752f));
}

__device__ __forceinline__ void mma16816(float c[4],
    uint32_t a0, uint32_t a1, uint32_t a2, uint32_t a3, uint32_t b0, uint32_t b1)
{
    asm volatile(
        "mma.sync.aligned.m16n8k16.row.col.f32.bf16.bf16.f32 "
        "{%0,%1,%2,%3},{%4,%5,%6,%7},{%8,%9},{%0,%1,%2,%3};\n"
        : "+f"(c[0]), "+f"(c[1]), "+f"(c[2]), "+f"(c[3])
        : "r"(a0), "r"(a1), "r"(a2), "r"(a3), "r"(b0), "r"(b1));
}

__device__ __forceinline__ void mma16808(float c[4],
    uint32_t a0, uint32_t a1, uint32_t b0)
{
    asm volatile(
        "mma.sync.aligned.m16n8k8.row.col.f32.bf16.bf16.f32 "
        "{%0,%1,%2,%3},{%4,%5},{%6},{%0,%1,%2,%3};\n"
        : "+f"(c[0]), "+f"(c[1]), "+f"(c[2]), "+f"(c[3])
        : "r"(a0), "r"(a1), "r"(b0));
}

template<int EPI>
__device__ __forceinline__ void store2(int m, int j0, float v0, float v1,
                                       const float* __restrict__ extra,
                                       float* __restrict__ outp)
{
    if (EPI == EPI_QKV) {
        int chunk = j0 / 96, within = j0 - chunk * 96;
        int hh = within / 24, dd = within - hh * 24;
        __nv_bfloat16* dst = (chunk == 0) ? g_q : (chunk == 1 ? g_k : g_v);
        if (chunk == 0) { v0 *= QSCALE_L2E; v1 *= QSCALE_L2E; }
        int win = m / NTOK, t = m - win * NTOK;
        size_t off = (((size_t)(win * NHEAD + hh)) * NTOK + t) * HDIM + dd;
        *reinterpret_cast<__nv_bfloat162*>(&dst[off]) =
            __float22bfloat162_rn(make_float2(v0, v1));
    } else if (EPI == EPI_GELU) {
        __nv_bfloat162 h;
        h.x = __float2bfloat16(gelu_exact(v0));
        h.y = __float2bfloat16(gelu_exact(v1));
        *reinterpret_cast<__nv_bfloat162*>(&g_hbf[(size_t)m * HIDDEN + j0]) = h;
    } else { // EPI_FC2
        size_t off = (size_t)m * CDIM + j0;
        float2 sc = *reinterpret_cast<const float2*>(&g_x2[off]);
        *reinterpret_cast<float2*>(&outp[off]) = make_float2(v0 + sc.x, v1 + sc.y);
    }
}

// Block tile 128x96, 8 warps as 4(m) x 2(n), warp tile 32x48, BK=96, minBlocks=3.
// EPI_PROJ fuses LN2: writes g_x2 (fp32) AND g_xn2 (bf16 LN).
template<int EPI, int KF, int NF>
__global__ __launch_bounds__(256, 3)
void hgemm_kernel(const float* __restrict__ bias,
                  const float* __restrict__ extra, float* __restrict__ outp,
                  const float* __restrict__ lnw, const float* __restrict__ lnb)
{
    const __nv_bfloat16* __restrict__ A =
        (EPI == EPI_QKV)  ? g_xw  :
        (EPI == EPI_PROJ) ? g_ao  :
        (EPI == EPI_GELU) ? g_xn2 : g_hbf;
    const __nv_bfloat16* __restrict__ Wt =
        (EPI == EPI_QKV)  ? g_wq  :
        (EPI == EPI_PROJ) ? g_wp  :
        (EPI == EPI_GELU) ? g_w1  : g_w2;

    __shared__ __nv_bfloat16 As[128 * ASTR];
    __shared__ __nv_bfloat16 Ws[96 * ASTR];

    const int tid  = threadIdx.x;
    const int warp = tid >> 5, lane = tid & 31;
    const int wm = warp >> 1, wn = warp & 1;
    const int m0 = blockIdx.x * 128, n0 = blockIdx.y * 96;
    const int l4 = lane >> 2, q2 = (lane & 3) * 2;

    float c[2][6][4] = {};

    for (int k0 = 0; k0 < KF; k0 += 96) {
        #pragma unroll
        for (int e = tid; e < 128 * 12; e += 256) {
            int row = e / 12, c8 = (e - row * 12) * 8;
            uint4 val = *reinterpret_cast<const uint4*>(&A[(size_t)(m0 + row) * KF + k0 + c8]);
            uint2* dst = reinterpret_cast<uint2*>(&As[row * ASTR + c8]);
            dst[0] = make_uint2(val.x, val.y);
            dst[1] = make_uint2(val.z, val.w);
        }
        for (int e = tid; e < 96 * 12; e += 256) {
            int row = e / 12, c8 = (e - row * 12) * 8;
            uint4 val = *reinterpret_cast<const uint4*>(&Wt[(size_t)(n0 + row) * KF + k0 + c8]);
            uint2* dst = reinterpret_cast<uint2*>(&Ws[row * ASTR + c8]);
            dst[0] = make_uint2(val.x, val.y);
            dst[1] = make_uint2(val.z, val.w);
        }
        __syncthreads();
        #pragma unroll
        for (int s = 0; s < 6; s++) {
            const int kb = s * 16;
            uint32_t a[2][4];
            #pragma unroll
            for (int mt = 0; mt < 2; mt++) {
                const int row = wm * 32 + mt * 16;
                a[mt][0] = *reinterpret_cast<const uint32_t*>(&As[(row + l4    ) * ASTR + kb + q2]);
                a[mt][1] = *reinterpret_cast<const uint32_t*>(&As[(row + l4 + 8) * ASTR + kb + q2]);
                a[mt][2] = *reinterpret_cast<const uint32_t*>(&As[(row + l4    ) * ASTR + kb + 8 + q2]);
                a[mt][3] = *reinterpret_cast<const uint32_t*>(&As[(row + l4 + 8) * ASTR + kb + 8 + q2]);
            }
            #pragma unroll
            for (int nt = 0; nt < 6; nt++) {
                const int brow = wn * 48 + nt * 8 + l4;
                uint32_t b0 = *reinterpret_cast<const uint32_t*>(&Ws[brow * ASTR + kb + q2]);
                uint32_t b1 = *reinterpret_cast<const uint32_t*>(&Ws[brow * ASTR + kb + 8 + q2]);
                mma16816(c[0][nt], a[0][0], a[0][1], a[0][2], a[0][3], b0, b1);
                mma16816(c[1][nt], a[1][0], a[1][1], a[1][2], a[1][3], b0, b1);
            }
        }
        __syncthreads();
    }

    if (EPI != EPI_PROJ) {
        #pragma unroll
        for (int mt = 0; mt < 2; mt++) {
            const int mr = m0 + wm * 32 + mt * 16 + l4;
            #pragma unroll
            for (int nt = 0; nt < 6; nt++) {
                int j0 = n0 + wn * 48 + nt * 8 + q2;
                float bv0 = bias[j0], bv1 = bias[j0 + 1];
                store2<EPI>(mr,     j0, c[mt][nt][0] + bv0, c[mt][nt][1] + bv1, extra, outp);
                store2<EPI>(mr + 8, j0, c[mt][nt][2] + bv0, c[mt][nt][3] + bv1, extra, outp);
            }
        }
    } else {
        float2* pstat = reinterpret_cast<float2*>(As);
        int roff[2][2];
        float psum[2][2] = {}, psq[2][2] = {};
        #pragma unroll
        for (int mt = 0; mt < 2; mt++) {
            #pragma unroll
            for (int half = 0; half < 2; half++) {
                int m = m0 + wm * 32 + mt * 16 + l4 + half * 8;
                int bidx; int l = win_to_l(m, bidx);
                roff[mt][half] = bidx * LTOT + l;
            }
        }
        #pragma unroll
        for (int mt = 0; mt < 2; mt++) {
            #pragma unroll
            for (int nt = 0; nt < 6; nt++) {
                int j0 = wn * 48 + nt * 8 + q2;
                float bv0 = bias[j0], bv1 = bias[j0 + 1];
                #pragma unroll
                for (int half = 0; half < 2; half++) {
                    size_t off = (size_t)roff[mt][half] * CDIM + j0;
                    float2 sc = *reinterpret_cast<const float2*>(&extra[off]);
                    float v0 = c[mt][nt][half * 2 + 0] + bv0 + sc.x;
                    float v1 = c[mt][nt][half * 2 + 1] + bv1 + sc.y;
                    *reinterpret_cast<float2*>(&g_x2[off]) = make_float2(v0, v1);
                    psum[mt][half] += v0 + v1;
                    psq[mt][half]  += v0 * v0 + v1 * v1;
                }
            }
        }
        #pragma unroll
        for (int mt = 0; mt < 2; mt++) {
            #pragma unroll
            for (int half = 0; half < 2; half++) {
                float s = psum[mt][half], q = psq[mt][half];
                s += __shfl_xor_sync(0xffffffffu, s, 1);
                s += __shfl_xor_sync(0xffffffffu, s, 2);
                q += __shfl_xor_sync(0xffffffffu, q, 1);
                q += __shfl_xor_sync(0xffffffffu, q, 2);
                if ((lane & 3) == 0) {
                    int rloc = wm * 32 + mt * 16 + l4 + half * 8;
                    pstat[rloc * 2 + wn] = make_float2(s, q);
                }
            }
        }
        __syncthreads();
        #pragma unroll
        for (int mt = 0; mt < 2; mt++) {
            #pragma unroll
            for (int half = 0; half < 2; half++) {
                int rloc = wm * 32 + mt * 16 + l4 + half * 8;
                float2 p0 = pstat[rloc * 2 + 0], p1 = pstat[rloc * 2 + 1];
                float mu  = (p0.x + p1.x) * (1.0f / 96.0f);
                float var = (p0.y + p1.y) * (1.0f / 96.0f) - mu * mu;
                float rs  = rsqrtf(var + 1e-5f);
                size_t rowbase = (size_t)roff[mt][half] * CDIM;
                #pragma unroll
                for (int nt = 0; nt < 6; nt++) {
                    int j0 = wn * 48 + nt * 8 + q2;
                    float2 v = *reinterpret_cast<const float2*>(&g_x2[rowbase + j0]);
                    __nv_bfloat162 hx;
                    hx.x = __float2bfloat16((v.x - mu) * rs * lnw[j0]     + lnb[j0]);
                    hx.y = __float2bfloat16((v.y - mu) * rs * lnw[j0 + 1] + lnb[j0 + 1]);
                    *reinterpret_cast<__nv_bfloat162*>(&g_xn2[rowbase + j0]) = hx;
                }
            }
        }
    }
}

// ---------------- HMMA windowed attention -------------------------------------
// 8 warps, THREE Q-tiles per warp (t, t+8, t+16); K/V fragments loaded once and
// shared across all three tiles -> per-tile smem traffic cut another 33%.
#define ATT_THR 256
#define KSTR 40
#define VSTR 372
#define ATTN_SMEM (352*KSTR*2 + 32*VSTR*2)

__global__ __launch_bounds__(ATT_THR, 2)
void attn_kernel()
{
    extern __shared__ char smraw[];
    __nv_bfloat16* Ks = reinterpret_cast<__nv_bfloat16*>(smraw);   // [352][KSTR]
    __nv_bfloat16* Vt = Ks + 352*KSTR;                             // [32][VSTR]

    const int bh  = blockIdx.x;
    const int win = bh >> 2, h = bh & 3;
    const int tid = threadIdx.x;
    const int warp = tid >> 5, lane = tid & 31;
    const int l4 = lane >> 2, q2 = (lane & 3) * 2;
    const size_t base = (size_t)bh * (NTOK * HDIM);

    const int w3 = win & 63;
    const int cls = (((w3 >> 4) == 3) ? 4 : 0) | ((((w3 >> 2) & 3) == 3) ? 2 : 0) | (((w3 & 3) == 3) ? 1 : 0);
    const __nv_bfloat16* __restrict__ bias_base = g_bias + ((size_t)(cls * NHEAD + h)) * NTOK * BSTR;

    for (int idx = tid; idx < 352 * 4; idx += ATT_THR) {
        int key = idx >> 2, d8 = (idx & 3) << 3;
        uint4 val = make_uint4(0u, 0u, 0u, 0u);
        if (key < NTOK && d8 < 24)
            val = *reinterpret_cast<const uint4*>(&g_k[base + (size_t)key * HDIM + d8]);
        *reinterpret_cast<uint4*>(&Ks[key * KSTR + d8]) = val;
    }
    for (int idx = tid; idx < 24 * 32; idx += ATT_THR) {
        int dim = idx >> 5, key = NTOK + (idx & 31);
        if (key < VSTR) Vt[dim * VSTR + key] = __float2bfloat16(0.0f);
    }
    for (int idx = tid; idx < 8 * VSTR; idx += ATT_THR) {
        int r = 24 + idx / VSTR, ccol = idx % VSTR;
        Vt[r * VSTR + ccol] = __float2bfloat16(r == 24 ? 1.0f : 0.0f);
    }
    __syncthreads();
    for (int idx = tid; idx < NTOK * HDIM; idx += ATT_THR) {
        int key = idx / HDIM, dim = idx - key * HDIM;
        Vt[dim * VSTR + key] = g_v[base + idx];
    }
    __syncthreads();

    // three tiles per warp: rows[t][half]
    int rows[3][2], rc[3][2], boff[3][2];
    uint32_t q[3][6];
    #pragma unroll
    for (int t = 0; t < 3; t++) {
        int tile = warp + t * 8;            // 0..23 (22,23 are padding work)
        rows[t][0] = tile * 16 + l4;
        rows[t][1] = rows[t][0] + 8;
        #pragma unroll
        for (int half = 0; half < 2; half++) {
            rc[t][half] = rows[t][half] < NTOK ? rows[t][half] : NTOK - 1;
            boff[t][half] = rc[t][half] * BSTR + q2;
        }
        const __nv_bfloat16* p0 = g_q + base + (size_t)rc[t][0] * HDIM;
        const __nv_bfloat16* p1 = g_q + base + (size_t)rc[t][1] * HDIM;
        q[t][0] = *reinterpret_cast<const uint32_t*>(p0 + q2);
        q[t][1] = *reinterpret_cast<const uint32_t*>(p1 + q2);
        q[t][2] = *reinterpret_cast<const uint32_t*>(p0 + 8 + q2);
        q[t][3] = *reinterpret_cast<const uint32_t*>(p1 + 8 + q2);
        q[t][4] = *reinterpret_cast<const uint32_t*>(p0 + 16 + q2);
        q[t][5] = *reinterpret_cast<const uint32_t*>(p1 + 16 + q2);
    }

    float o[3][4][4] = {};   // [t][nt][e]; nt=3 is the ones-row denominator

    for (int kb = 0; kb < 352; kb += 32) {
        // K fragments loaded once, shared by all three tiles
        uint32_t kf0[4], kf1[4], kf2[4];
        #pragma unroll
        for (int nt = 0; nt < 4; nt++) {
            const __nv_bfloat16* kr = &Ks[(kb + nt * 8 + l4) * KSTR];
            kf0[nt] = *reinterpret_cast<const uint32_t*>(kr + q2);
            kf1[nt] = *reinterpret_cast<const uint32_t*>(kr + 8 + q2);
            kf2[nt] = *reinterpret_cast<const uint32_t*>(kr + 16 + q2);
        }
        uint32_t pa[3][2][4];
        #pragma unroll
        for (int t = 0; t < 3; t++) {
            // bias for this tile/block (L2-hot)
            uint32_t b0r[4], b1r[4];
            #pragma unroll
            for (int nt = 0; nt < 4; nt++) {
                b0r[nt] = *reinterpret_cast<const uint32_t*>(bias_base + boff[t][0] + kb + nt * 8);
                b1r[nt] = *reinterpret_cast<const uint32_t*>(bias_base + boff[t][1] + kb + nt * 8);
            }
            float c[4][4] = {};
            #pragma unroll
            for (int nt = 0; nt < 4; nt++) {
                mma16816(c[nt], q[t][0], q[t][1], q[t][2], q[t][3], kf0[nt], kf1[nt]);
                mma16808(c[nt], q[t][4], q[t][5], kf2[nt]);
            }
            #pragma unroll
            for (int nt = 0; nt < 4; nt++) {
                uint32_t sa, sb;
                asm("cvt.rn.bf16x2.f32 %0, %1, %2;" : "=r"(sa) : "f"(c[nt][1]), "f"(c[nt][0]));
                asm("cvt.rn.bf16x2.f32 %0, %1, %2;" : "=r"(sb) : "f"(c[nt][3]), "f"(c[nt][2]));
                asm("add.rn.bf16x2 %0, %1, %2;" : "=r"(sa) : "r"(sa), "r"(b0r[nt]));
                asm("add.rn.bf16x2 %0, %1, %2;" : "=r"(sb) : "r"(sb), "r"(b1r[nt]));
                asm("ex2.approx.ftz.bf16x2 %0, %1;" : "=r"(pa[t][nt >> 1][(nt & 1) * 2 + 0]) : "r"(sa));
                asm("ex2.approx.ftz.bf16x2 %0, %1;" : "=r"(pa[t][nt >> 1][(nt & 1) * 2 + 1]) : "r"(sb));
            }
        }
        // PV: V fragments loaded once, shared by all three tiles
        #pragma unroll
        for (int ks = 0; ks < 2; ks++) {
            #pragma unroll
            for (int nt = 0; nt < 4; nt++) {
                const __nv_bfloat16* vr = &Vt[(nt * 8 + l4) * VSTR + kb + ks * 16];
                uint32_t b0 = *reinterpret_cast<const uint32_t*>(vr + q2);
                uint32_t b1 = *reinterpret_cast<const uint32_t*>(vr + 8 + q2);
                #pragma unroll
                for (int t = 0; t < 3; t++)
                    mma16816(o[t][nt], pa[t][ks][0], pa[t][ks][1], pa[t][ks][2], pa[t][ks][3], b0, b1);
            }
        }
    }

    #pragma unroll
    for (int t = 0; t < 3; t++) {
        float s0 = __shfl_sync(0xffffffffu, o[t][3][0], lane & 28);
        float s1 = __shfl_sync(0xffffffffu, o[t][3][2], lane & 28);
        float inv0 = 1.0f / s0, inv1 = 1.0f / s1;
        if (rows[t][0] < NTOK) {
            __nv_bfloat16* op = g_ao + ((size_t)win * NTOK + rows[t][0]) * CDIM + h * HDIM;
            #pragma unroll
            for (int nt = 0; nt < 3; nt++)
                *reinterpret_cast<__nv_bfloat162*>(op + nt * 8 + q2) =
                    __float22bfloat162_rn(make_float2(o[t][nt][0] * inv0, o[t][nt][1] * inv0));
        }
        if (rows[t][1] < NTOK) {
            __nv_bfloat16* op = g_ao + ((size_t)win * NTOK + rows[t][1]) * CDIM + h * HDIM;
            #pragma unroll
            for (int nt = 0; nt < 3; nt++)
                *reinterpret_cast<__nv_bfloat162*>(op + nt * 8 + q2) =
                    __float22bfloat162_rn(make_float2(o[t][nt][2] * inv1, o[t][nt][3] * inv1));
        }
    }
}

// ---------------- launch ----------------
extern "C" void kernel_launch(void* const* d_in, const int* in_sizes, int n_in,
                              void* d_out, int out_size)
{
    const float* x    = (const float*)d_in[0];
    const float* n1w  = (const float*)d_in[1];
    const float* n1b  = (const float*)d_in[2];
    const float* qkvw = (const float*)d_in[3];
    const float* qkvb = (const float*)d_in[4];
    const float* rpb  = (const float*)d_in[5];
    const float* pw   = (const float*)d_in[6];
    const float* pb   = (const float*)d_in[7];
    const float* n2w  = (const float*)d_in[8];
    const float* n2b  = (const float*)d_in[9];
    const float* f1w  = (const float*)d_in[10];
    const float* f1b  = (const float*)d_in[11];
    const float* f2w  = (const float*)d_in[12];
    const float* f2b  = (const float*)d_in[13];
    float* out = (float*)d_out;

    cudaFuncSetAttribute(attn_kernel, cudaFuncAttributeMaxDynamicSharedMemorySize, ATTN_SMEM);

    prep_all<<<PREP_BIAS_BLOCKS + 144, BSTR>>>(rpb, qkvw, pw, f1w, f2w);
    ln1_kernel<<<MTOT / 8, 256>>>(x, n1w, n1b);
    hgemm_kernel<EPI_QKV, 96, 288><<<dim3(686, 3), 256>>>(qkvb, nullptr, nullptr, nullptr, nullptr);
    attn_kernel<<<NWINS * NHEAD, ATT_THR, ATTN_SMEM>>>();
    hgemm_kernel<EPI_PROJ, 96, 96><<<dim3(686, 1), 256>>>(pb, x, nullptr, n2w, n2b);
    hgemm_kernel<EPI_GELU, 96, 384><<<dim3(686, 4), 256>>>(f1b, nullptr, nullptr, nullptr, nullptr);
    hgemm_kernel<EPI_FC2, 384, 96><<<dim3(686, 1), 256>>>(f2b, nullptr, out, nullptr, nullptr);
}

// round 17
// speedup vs baseline: 1.1141x; 1.1141x over previous
#include <cuda_runtime.h>
#include <cuda_bf16.h>
#include <cstdint>
#include <math.h>

// ---------------- static config ----------------
#define CDIM   96
#define NHEAD  4
#define HDIM   24
#define NTOK   343
#define NWINS  256
#define LTOT   21952
#define MTOT   87808
#define HIDDEN 384
#define QSCALE_L2E 0.29448890f
#define LOG2E 1.4426950408889634f

// ---------------- scratch (device globals; referenced ONLY in device code) ----
__device__ __nv_bfloat16 g_xw [MTOT*CDIM];
__device__ __nv_bfloat16 g_q  [NWINS*NHEAD*NTOK*HDIM];
__device__ __nv_bfloat16 g_k  [NWINS*NHEAD*NTOK*HDIM];
__device__ __nv_bfloat16 g_v  [NWINS*NHEAD*NTOK*HDIM];
__device__ __nv_bfloat16 g_ao [MTOT*CDIM];
__device__ float         g_x2 [MTOT*CDIM];
__device__ __nv_bfloat16 g_xn2[MTOT*CDIM];
__device__ __nv_bfloat16 g_hbf[MTOT*HIDDEN];
__device__ __nv_bfloat16 g_wq[288*96];
__device__ __nv_bfloat16 g_wp[96*96];
__device__ __nv_bfloat16 g_w1[384*96];
__device__ __nv_bfloat16 g_w2[96*384];
#define BSTR 352
__device__ __nv_bfloat16 g_bias[8*NHEAD*NTOK*BSTR];

// windowed token index -> (batch, spatial l) applying shift (+3 mod 28)
__device__ __forceinline__ int win_to_l(int m, int& bidx) {
    int win = m / NTOK, t = m - win * NTOK;
    bidx = win >> 6; int w3 = win & 63;
    int wh = w3 >> 4, ww = (w3 >> 2) & 3, wd = w3 & 3;
    int a = t / 49, rr = t - a * 49, bb = rr / 7, cc = rr - bb * 7;
    int gh = wh * 7 + a  + 3; if (gh >= 28) gh -= 28;
    int gw = ww * 7 + bb + 3; if (gw >= 28) gw -= 28;
    int gd = wd * 7 + cc + 3; if (gd >= 28) gd -= 28;
    return (gh * 28 + gw) * 28 + gd;
}

// ---------------- merged prep: bias + weights ----------------
__device__ __forceinline__ int seg_grp(int cls_bit, int a) {
    return cls_bit ? (1 + (a >= 4)) : 0;
}

#define PREP_BIAS_BLOCKS (8*NHEAD*NTOK)

__global__ __launch_bounds__(BSTR)
void prep_all(const float* __restrict__ rpb_table,
              const float* __restrict__ qkvw, const float* __restrict__ pw,
              const float* __restrict__ f1w,  const float* __restrict__ f2w)
{
    if (blockIdx.x < PREP_BIAS_BLOCKS) {
        const int bid = blockIdx.x;
        const int i   = bid % NTOK;
        const int t   = bid / NTOK;
        const int h   = t & 3;
        const int cls = t >> 2;
        const int j   = threadIdx.x;

        float val;
        if (j >= NTOK) {
            val = -100.0f;
        } else {
            int ai = i / 49, ri = i - ai * 49, bi = ri / 7, ci = ri - bi * 7;
            int aj = j / 49, rj = j - aj * 49, bj = rj / 7, cj = rj - bj * 7;
            int ridx = 13 * ((ai - aj) + (bi - bj)) + (ci - cj) + 162;
            val = rpb_table[ridx * NHEAD + h];
            int gi = seg_grp((cls >> 2) & 1, ai) * 9 + seg_grp((cls >> 1) & 1, bi) * 3 + seg_grp(cls & 1, ci);
            int gj = seg_grp((cls >> 2) & 1, aj) * 9 + seg_grp((cls >> 1) & 1, bj) * 3 + seg_grp(cls & 1, cj);
            if (gi != gj) val -= 100.0f;
        }
        g_bias[(size_t)bid * BSTR + j] = __float2bfloat16(val * LOG2E);
    } else {
        int i = (blockIdx.x - PREP_BIAS_BLOCKS) * BSTR + threadIdx.x;
        if (i < 288*96) { int n = i / 96,  k = i - n*96;  g_wq[i] = __float2bfloat16(qkvw[k*288 + n]); }
        if (i < 96*96)  { int n = i / 96,  k = i - n*96;  g_wp[i] = __float2bfloat16(pw  [k*96  + n]); }
        if (i < 384*96) { int n = i / 96,  k = i - n*96;  g_w1[i] = __float2bfloat16(f1w [k*384 + n]); }
        if (i < 96*384) { int n = i / 384, k = i - n*384; g_w2[i] = __float2bfloat16(f2w [k*96  + n]); }
    }
}

// ---------------- LayerNorm 1 (warp per token) ----------------
__global__ __launch_bounds__(256)
void ln1_kernel(const float* __restrict__ xin, const float* __restrict__ w,
                const float* __restrict__ b)
{
    int m = blockIdx.x * 8 + (threadIdx.x >> 5);
    int lane = threadIdx.x & 31;
    int bidx; int l = win_to_l(m, bidx);
    const float* src = xin + ((size_t)bidx * LTOT + l) * CDIM;
    __nv_bfloat16* dst = g_xw + (size_t)m * CDIM;
    float v0 = src[lane], v1 = src[lane + 32], v2 = src[lane + 64];
    float s  = v0 + v1 + v2;
    float s2 = v0 * v0 + v1 * v1 + v2 * v2;
    #pragma unroll
    for (int o = 16; o; o >>= 1) {
        s  += __shfl_xor_sync(0xffffffffu, s,  o);
        s2 += __shfl_xor_sync(0xffffffffu, s2, o);
    }
    float mu  = s * (1.0f / 96.0f);
    float var = s2 * (1.0f / 96.0f) - mu * mu;
    float rs  = rsqrtf(var + 1e-5f);
    dst[lane]      = __float2bfloat16((v0 - mu) * rs * w[lane]      + b[lane]);
    dst[lane + 32] = __float2bfloat16((v1 - mu) * rs * w[lane + 32] + b[lane + 32]);
    dst[lane + 64] = __float2bfloat16((v2 - mu) * rs * w[lane + 64] + b[lane + 64]);
}

// ---------------- bf16 HMMA GEMM (m16n8k16) with fused epilogues ----------------
enum { EPI_QKV = 0, EPI_PROJ = 1, EPI_GELU = 2, EPI_FC2 = 3 };
#define ASTR 104

__device__ __forceinline__ float gelu_exact(float x) {
    return 0.5f * x * (1.0f + erff(x * 0.70710678118654752f));
}

__device__ __forceinline__ void mma16816(float c[4],
    uint32_t a0, uint32_t a1, uint32_t a2, uint32_t a3, uint32_t b0, uint32_t b1)
{
    asm volatile(
        "mma.sync.aligned.m16n8k16.row.col.f32.bf16.bf16.f32 "
        "{%0,%1,%2,%3},{%4,%5,%6,%7},{%8,%9},{%0,%1,%2,%3};\n"
        : "+f"(c[0]), "+f"(c[1]), "+f"(c[2]), "+f"(c[3])
        : "r"(a0), "r"(a1), "r"(a2), "r"(a3), "r"(b0), "r"(b1));
}

__device__ __forceinline__ void mma16808(float c[4],
    uint32_t a0, uint32_t a1, uint32_t b0)
{
    asm volatile(
        "mma.sync.aligned.m16n8k8.row.col.f32.bf16.bf16.f32 "
        "{%0,%1,%2,%3},{%4,%5},{%6},{%0,%1,%2,%3};\n"
        : "+f"(c[0]), "+f"(c[1]), "+f"(c[2]), "+f"(c[3])
        : "r"(a0), "r"(a1), "r"(b0));
}

__device__ __forceinline__ void cpasync16(void* smem_dst, const void* gsrc) {
    uint32_t sa = (uint32_t)__cvta_generic_to_shared(smem_dst);
    asm volatile("cp.async.ca.shared.global [%0], [%1], 16;\n" :: "r"(sa), "l"(gsrc));
}

template<int EPI>
__device__ __forceinline__ void store2(int m, int j0, float v0, float v1,
                                       const float* __restrict__ extra,
                                       float* __restrict__ outp)
{
    if (EPI == EPI_QKV) {
        int chunk = j0 / 96, within = j0 - chunk * 96;
        int hh = within / 24, dd = within - hh * 24;
        __nv_bfloat16* dst = (chunk == 0) ? g_q : (chunk == 1 ? g_k : g_v);
        if (chunk == 0) { v0 *= QSCALE_L2E; v1 *= QSCALE_L2E; }
        int win = m / NTOK, t = m - win * NTOK;
        size_t off = (((size_t)(win * NHEAD + hh)) * NTOK + t) * HDIM + dd;
        *reinterpret_cast<__nv_bfloat162*>(&dst[off]) =
            __float22bfloat162_rn(make_float2(v0, v1));
    } else if (EPI == EPI_GELU) {
        __nv_bfloat162 h;
        h.x = __float2bfloat16(gelu_exact(v0));
        h.y = __float2bfloat16(gelu_exact(v1));
        *reinterpret_cast<__nv_bfloat162*>(&g_hbf[(size_t)m * HIDDEN + j0]) = h;
    } else { // EPI_FC2
        size_t off = (size_t)m * CDIM + j0;
        float2 sc = *reinterpret_cast<const float2*>(&g_x2[off]);
        *reinterpret_cast<float2*>(&outp[off]) = make_float2(v0 + sc.x, v1 + sc.y);
    }
}

// Block tile 128x96, 8 warps as 4(m) x 2(n), warp tile 32x48, BK=96.
// Staging via cp.async (no LDG->STS register chains).
// EPI_PROJ fuses LN2: writes g_x2 (fp32) AND g_xn2 (bf16 LN).
template<int EPI, int KF, int NF>
__global__ __launch_bounds__(256, 3)
void hgemm_kernel(const float* __restrict__ bias,
                  const float* __restrict__ extra, float* __restrict__ outp,
                  const float* __restrict__ lnw, const float* __restrict__ lnb)
{
    const __nv_bfloat16* __restrict__ A =
        (EPI == EPI_QKV)  ? g_xw  :
        (EPI == EPI_PROJ) ? g_ao  :
        (EPI == EPI_GELU) ? g_xn2 : g_hbf;
    const __nv_bfloat16* __restrict__ Wt =
        (EPI == EPI_QKV)  ? g_wq  :
        (EPI == EPI_PROJ) ? g_wp  :
        (EPI == EPI_GELU) ? g_w1  : g_w2;

    __shared__ __nv_bfloat16 As[128 * ASTR];
    __shared__ __nv_bfloat16 Ws[96 * ASTR];

    const int tid  = threadIdx.x;
    const int warp = tid >> 5, lane = tid & 31;
    const int wm = warp >> 1, wn = warp & 1;
    const int m0 = blockIdx.x * 128, n0 = blockIdx.y * 96;
    const int l4 = lane >> 2, q2 = (lane & 3) * 2;

    float c[2][6][4] = {};

    for (int k0 = 0; k0 < KF; k0 += 96) {
        #pragma unroll
        for (int e = tid; e < 128 * 12; e += 256) {
            int row = e / 12, c8 = (e - row * 12) * 8;
            cpasync16(&As[row * ASTR + c8], &A[(size_t)(m0 + row) * KF + k0 + c8]);
        }
        for (int e = tid; e < 96 * 12; e += 256) {
            int row = e / 12, c8 = (e - row * 12) * 8;
            cpasync16(&Ws[row * ASTR + c8], &Wt[(size_t)(n0 + row) * KF + k0 + c8]);
        }
        asm volatile("cp.async.commit_group;\n" ::: "memory");
        asm volatile("cp.async.wait_group 0;\n" ::: "memory");
        __syncthreads();
        #pragma unroll
        for (int s = 0; s < 6; s++) {
            const int kb = s * 16;
            uint32_t a[2][4];
            #pragma unroll
            for (int mt = 0; mt < 2; mt++) {
                const int row = wm * 32 + mt * 16;
                a[mt][0] = *reinterpret_cast<const uint32_t*>(&As[(row + l4    ) * ASTR + kb + q2]);
                a[mt][1] = *reinterpret_cast<const uint32_t*>(&As[(row + l4 + 8) * ASTR + kb + q2]);
                a[mt][2] = *reinterpret_cast<const uint32_t*>(&As[(row + l4    ) * ASTR + kb + 8 + q2]);
                a[mt][3] = *reinterpret_cast<const uint32_t*>(&As[(row + l4 + 8) * ASTR + kb + 8 + q2]);
            }
            #pragma unroll
            for (int nt = 0; nt < 6; nt++) {
                const int brow = wn * 48 + nt * 8 + l4;
                uint32_t b0 = *reinterpret_cast<const uint32_t*>(&Ws[brow * ASTR + kb + q2]);
                uint32_t b1 = *reinterpret_cast<const uint32_t*>(&Ws[brow * ASTR + kb + 8 + q2]);
                mma16816(c[0][nt], a[0][0], a[0][1], a[0][2], a[0][3], b0, b1);
                mma16816(c[1][nt], a[1][0], a[1][1], a[1][2], a[1][3], b0, b1);
            }
        }
        __syncthreads();
    }

    if (EPI != EPI_PROJ) {
        #pragma unroll
        for (int mt = 0; mt < 2; mt++) {
            const int mr = m0 + wm * 32 + mt * 16 + l4;
            #pragma unroll
            for (int nt = 0; nt < 6; nt++) {
                int j0 = n0 + wn * 48 + nt * 8 + q2;
                float bv0 = bias[j0], bv1 = bias[j0 + 1];
                store2<EPI>(mr,     j0, c[mt][nt][0] + bv0, c[mt][nt][1] + bv1, extra, outp);
                store2<EPI>(mr + 8, j0, c[mt][nt][2] + bv0, c[mt][nt][3] + bv1, extra, outp);
            }
        }
    } else {
        float2* pstat = reinterpret_cast<float2*>(As);
        int roff[2][2];
        float psum[2][2] = {}, psq[2][2] = {};
        #pragma unroll
        for (int mt = 0; mt < 2; mt++) {
            #pragma unroll
            for (int half = 0; half < 2; half++) {
                int m = m0 + wm * 32 + mt * 16 + l4 + half * 8;
                int bidx; int l = win_to_l(m, bidx);
                roff[mt][half] = bidx * LTOT + l;
            }
        }
        #pragma unroll
        for (int mt = 0; mt < 2; mt++) {
            #pragma unroll
            for (int nt = 0; nt < 6; nt++) {
                int j0 = wn * 48 + nt * 8 + q2;
                float bv0 = bias[j0], bv1 = bias[j0 + 1];
                #pragma unroll
                for (int half = 0; half < 2; half++) {
                    size_t off = (size_t)roff[mt][half] * CDIM + j0;
                    float2 sc = *reinterpret_cast<const float2*>(&extra[off]);
                    float v0 = c[mt][nt][half * 2 + 0] + bv0 + sc.x;
                    float v1 = c[mt][nt][half * 2 + 1] + bv1 + sc.y;
                    *reinterpret_cast<float2*>(&g_x2[off]) = make_float2(v0, v1);
                    psum[mt][half] += v0 + v1;
                    psq[mt][half]  += v0 * v0 + v1 * v1;
                }
            }
        }
        #pragma unroll
        for (int mt = 0; mt < 2; mt++) {
            #pragma unroll
            for (int half = 0; half < 2; half++) {
                float s = psum[mt][half], q = psq[mt][half];
                s += __shfl_xor_sync(0xffffffffu, s, 1);
                s += __shfl_xor_sync(0xffffffffu, s, 2);
                q += __shfl_xor_sync(0xffffffffu, q, 1);
                q += __shfl_xor_sync(0xffffffffu, q, 2);
                if ((lane & 3) == 0) {
                    int rloc = wm * 32 + mt * 16 + l4 + half * 8;
                    pstat[rloc * 2 + wn] = make_float2(s, q);
                }
            }
        }
        __syncthreads();
        #pragma unroll
        for (int mt = 0; mt < 2; mt++) {
            #pragma unroll
            for (int half = 0; half < 2; half++) {
                int rloc = wm * 32 + mt * 16 + l4 + half * 8;
                float2 p0 = pstat[rloc * 2 + 0], p1 = pstat[rloc * 2 + 1];
                float mu  = (p0.x + p1.x) * (1.0f / 96.0f);
                float var = (p0.y + p1.y) * (1.0f / 96.0f) - mu * mu;
                float rs  = rsqrtf(var + 1e-5f);
                size_t rowbase = (size_t)roff[mt][half] * CDIM;
                #pragma unroll
                for (int nt = 0; nt < 6; nt++) {
                    int j0 = wn * 48 + nt * 8 + q2;
                    float2 v = *reinterpret_cast<const float2*>(&g_x2[rowbase + j0]);
                    __nv_bfloat162 hx;
                    hx.x = __float2bfloat16((v.x - mu) * rs * lnw[j0]     + lnb[j0]);
                    hx.y = __float2bfloat16((v.y - mu) * rs * lnw[j0 + 1] + lnb[j0 + 1]);
                    *reinterpret_cast<__nv_bfloat162*>(&g_xn2[rowbase + j0]) = hx;
                }
            }
        }
    }
}

// ---------------- HMMA windowed attention (R15 best: 2 tiles/warp, 11 warps) --
#define ATT_THR 352
#define KSTR 40
#define VSTR 372
#define ATTN_SMEM (352*KSTR*2 + 32*VSTR*2)

__global__ __launch_bounds__(ATT_THR, 2)
void attn_kernel()
{
    extern __shared__ char smraw[];
    __nv_bfloat16* Ks = reinterpret_cast<__nv_bfloat16*>(smraw);   // [352][KSTR]
    __nv_bfloat16* Vt = Ks + 352*KSTR;                             // [32][VSTR]

    const int bh  = blockIdx.x;
    const int win = bh >> 2, h = bh & 3;
    const int tid = threadIdx.x;
    const int warp = tid >> 5, lane = tid & 31;
    const int l4 = lane >> 2, q2 = (lane & 3) * 2;
    const size_t base = (size_t)bh * (NTOK * HDIM);

    const int w3 = win & 63;
    const int cls = (((w3 >> 4) == 3) ? 4 : 0) | ((((w3 >> 2) & 3) == 3) ? 2 : 0) | (((w3 & 3) == 3) ? 1 : 0);
    const __nv_bfloat16* __restrict__ bias_base = g_bias + ((size_t)(cls * NHEAD + h)) * NTOK * BSTR;

    for (int idx = tid; idx < 352 * 4; idx += ATT_THR) {
        int key = idx >> 2, d8 = (idx & 3) << 3;
        uint4 val = make_uint4(0u, 0u, 0u, 0u);
        if (key < NTOK && d8 < 24)
            val = *reinterpret_cast<const uint4*>(&g_k[base + (size_t)key * HDIM + d8]);
        *reinterpret_cast<uint4*>(&Ks[key * KSTR + d8]) = val;
    }
    for (int idx = tid; idx < 24 * 32; idx += ATT_THR) {
        int dim = idx >> 5, key = NTOK + (idx & 31);
        if (key < VSTR) Vt[dim * VSTR + key] = __float2bfloat16(0.0f);
    }
    for (int idx = tid; idx < 8 * VSTR; idx += ATT_THR) {
        int r = 24 + idx / VSTR, ccol = idx % VSTR;
        Vt[r * VSTR + ccol] = __float2bfloat16(r == 24 ? 1.0f : 0.0f);
    }
    __syncthreads();
    for (int idx = tid; idx < NTOK * HDIM; idx += ATT_THR) {
        int key = idx / HDIM, dim = idx - key * HDIM;
        Vt[dim * VSTR + key] = g_v[base + idx];
    }
    __syncthreads();

    // tileA = warp (0..10), tileB = warp + 11 (11..21)
    const int rA0 = warp * 16 + l4,        rA1 = rA0 + 8;
    const int rB0 = (warp + 11) * 16 + l4, rB1 = rB0 + 8;
    const int rA0c = rA0 < NTOK ? rA0 : NTOK - 1;
    const int rA1c = rA1 < NTOK ? rA1 : NTOK - 1;
    const int rB0c = rB0 < NTOK ? rB0 : NTOK - 1;
    const int rB1c = rB1 < NTOK ? rB1 : NTOK - 1;

    uint32_t qA[6], qB[6];
    {
        const __nv_bfloat16* p0 = g_q + base + (size_t)rA0c * HDIM;
        const __nv_bfloat16* p1 = g_q + base + (size_t)rA1c * HDIM;
        qA[0] = *reinterpret_cast<const uint32_t*>(p0 + q2);
        qA[1] = *reinterpret_cast<const uint32_t*>(p1 + q2);
        qA[2] = *reinterpret_cast<const uint32_t*>(p0 + 8 + q2);
        qA[3] = *reinterpret_cast<const uint32_t*>(p1 + 8 + q2);
        qA[4] = *reinterpret_cast<const uint32_t*>(p0 + 16 + q2);
        qA[5] = *reinterpret_cast<const uint32_t*>(p1 + 16 + q2);
        const __nv_bfloat16* p2 = g_q + base + (size_t)rB0c * HDIM;
        const __nv_bfloat16* p3 = g_q + base + (size_t)rB1c * HDIM;
        qB[0] = *reinterpret_cast<const uint32_t*>(p2 + q2);
        qB[1] = *reinterpret_cast<const uint32_t*>(p3 + q2);
        qB[2] = *reinterpret_cast<const uint32_t*>(p2 + 8 + q2);
        qB[3] = *reinterpret_cast<const uint32_t*>(p3 + 8 + q2);
        qB[4] = *reinterpret_cast<const uint32_t*>(p2 + 16 + q2);
        qB[5] = *reinterpret_cast<const uint32_t*>(p3 + 16 + q2);
    }
    const __nv_bfloat16* __restrict__ brA0 = bias_base + (size_t)rA0c * BSTR + q2;
    const __nv_bfloat16* __restrict__ brA1 = bias_base + (size_t)rA1c * BSTR + q2;
    const __nv_bfloat16* __restrict__ brB0 = bias_base + (size_t)rB0c * BSTR + q2;
    const __nv_bfloat16* __restrict__ brB1 = bias_base + (size_t)rB1c * BSTR + q2;

    float oA[4][4] = {}, oB[4][4] = {};   // [3] = denominator (ones-row)

    for (int kb = 0; kb < 352; kb += 32) {
        uint32_t kf0[4], kf1[4], kf2[4];
        #pragma unroll
        for (int nt = 0; nt < 4; nt++) {
            const __nv_bfloat16* kr = &Ks[(kb + nt * 8 + l4) * KSTR];
            kf0[nt] = *reinterpret_cast<const uint32_t*>(kr + q2);
            kf1[nt] = *reinterpret_cast<const uint32_t*>(kr + 8 + q2);
            kf2[nt] = *reinterpret_cast<const uint32_t*>(kr + 16 + q2);
        }
        uint32_t bA0[4], bA1[4], bB0[4], bB1[4];
        #pragma unroll
        for (int nt = 0; nt < 4; nt++) {
            bA0[nt] = *reinterpret_cast<const uint32_t*>(brA0 + kb + nt * 8);
            bA1[nt] = *reinterpret_cast<const uint32_t*>(brA1 + kb + nt * 8);
            bB0[nt] = *reinterpret_cast<const uint32_t*>(brB0 + kb + nt * 8);
            bB1[nt] = *reinterpret_cast<const uint32_t*>(brB1 + kb + nt * 8);
        }
        uint32_t paA[2][4];
        {
            float c[4][4] = {};
            #pragma unroll
            for (int nt = 0; nt < 4; nt++) {
                mma16816(c[nt], qA[0], qA[1], qA[2], qA[3], kf0[nt], kf1[nt]);
                mma16808(c[nt], qA[4], qA[5], kf2[nt]);
            }
            #pragma unroll
            for (int nt = 0; nt < 4; nt++) {
                uint32_t sa, sb;
                asm("cvt.rn.bf16x2.f32 %0, %1, %2;" : "=r"(sa) : "f"(c[nt][1]), "f"(c[nt][0]));
                asm("cvt.rn.bf16x2.f32 %0, %1, %2;" : "=r"(sb) : "f"(c[nt][3]), "f"(c[nt][2]));
                asm("add.rn.bf16x2 %0, %1, %2;" : "=r"(sa) : "r"(sa), "r"(bA0[nt]));
                asm("add.rn.bf16x2 %0, %1, %2;" : "=r"(sb) : "r"(sb), "r"(bA1[nt]));
                asm("ex2.approx.ftz.bf16x2 %0, %1;" : "=r"(paA[nt >> 1][(nt & 1) * 2 + 0]) : "r"(sa));
                asm("ex2.approx.ftz.bf16x2 %0, %1;" : "=r"(paA[nt >> 1][(nt & 1) * 2 + 1]) : "r"(sb));
            }
        }
        uint32_t paB[2][4];
        {
            float c[4][4] = {};
            #pragma unroll
            for (int nt = 0; nt < 4; nt++) {
                mma16816(c[nt], qB[0], qB[1], qB[2], qB[3], kf0[nt], kf1[nt]);
                mma16808(c[nt], qB[4], qB[5], kf2[nt]);
            }
            #pragma unroll
            for (int nt = 0; nt < 4; nt++) {
                uint32_t sa, sb;
                asm("cvt.rn.bf16x2.f32 %0, %1, %2;" : "=r"(sa) : "f"(c[nt][1]), "f"(c[nt][0]));
                asm("cvt.rn.bf16x2.f32 %0, %1, %2;" : "=r"(sb) : "f"(c[nt][3]), "f"(c[nt][2]));
                asm("add.rn.bf16x2 %0, %1, %2;" : "=r"(sa) : "r"(sa), "r"(bB0[nt]));
                asm("add.rn.bf16x2 %0, %1, %2;" : "=r"(sb) : "r"(sb), "r"(bB1[nt]));
                asm("ex2.approx.ftz.bf16x2 %0, %1;" : "=r"(paB[nt >> 1][(nt & 1) * 2 + 0]) : "r"(sa));
                asm("ex2.approx.ftz.bf16x2 %0, %1;" : "=r"(paB[nt >> 1][(nt & 1) * 2 + 1]) : "r"(sb));
            }
        }
        #pragma unroll
        for (int ks = 0; ks < 2; ks++) {
            #pragma unroll
            for (int nt = 0; nt < 4; nt++) {
                const __nv_bfloat16* vr = &Vt[(nt * 8 + l4) * VSTR + kb + ks * 16];
                uint32_t b0 = *reinterpret_cast<const uint32_t*>(vr + q2);
                uint32_t b1 = *reinterpret_cast<const uint32_t*>(vr + 8 + q2);
                mma16816(oA[nt], paA[ks][0], paA[ks][1], paA[ks][2], paA[ks][3], b0, b1);
                mma16816(oB[nt], paB[ks][0], paB[ks][1], paB[ks][2], paB[ks][3], b0, b1);
            }
        }
    }

    {
        float s0 = __shfl_sync(0xffffffffu, oA[3][0], lane & 28);
        float s1 = __shfl_sync(0xffffffffu, oA[3][2], lane & 28);
        float inv0 = 1.0f / s0, inv1 = 1.0f / s1;
        if (rA0 < NTOK) {
            __nv_bfloat16* op = g_ao + ((size_t)win * NTOK + rA0) * CDIM + h * HDIM;
            #pragma unroll
            for (int nt = 0; nt < 3; nt++)
                *reinterpret_cast<__nv_bfloat162*>(op + nt * 8 + q2) =
                    __float22bfloat162_rn(make_float2(oA[nt][0] * inv0, oA[nt][1] * inv0));
        }
        if (rA1 < NTOK) {
            __nv_bfloat16* op = g_ao + ((size_t)win * NTOK + rA1) * CDIM + h * HDIM;
            #pragma unroll
            for (int nt = 0; nt < 3; nt++)
                *reinterpret_cast<__nv_bfloat162*>(op + nt * 8 + q2) =
                    __float22bfloat162_rn(make_float2(oA[nt][2] * inv1, oA[nt][3] * inv1));
        }
    }
    {
        float s0 = __shfl_sync(0xffffffffu, oB[3][0], lane & 28);
        float s1 = __shfl_sync(0xffffffffu, oB[3][2], lane & 28);
        float inv0 = 1.0f / s0, inv1 = 1.0f / s1;
        if (rB0 < NTOK) {
            __nv_bfloat16* op = g_ao + ((size_t)win * NTOK + rB0) * CDIM + h * HDIM;
            #pragma unroll
            for (int nt = 0; nt < 3; nt++)
                *reinterpret_cast<__nv_bfloat162*>(op + nt * 8 + q2) =
                    __float22bfloat162_rn(make_float2(oB[nt][0] * inv0, oB[nt][1] * inv0));
        }
        if (rB1 < NTOK) {
            __nv_bfloat16* op = g_ao + ((size_t)win * NTOK + rB1) * CDIM + h * HDIM;
            #pragma unroll
            for (int nt = 0; nt < 3; nt++)
                *reinterpret_cast<__nv_bfloat162*>(op + nt * 8 + q2) =
                    __float22bfloat162_rn(make_float2(oB[nt][2] * inv1, oB[nt][3] * inv1));
        }
    }
}

// ---------------- launch ----------------
extern "C" void kernel_launch(void* const* d_in, const int* in_sizes, int n_in,
                              void* d_out, int out_size)
{
    const float* x    = (const float*)d_in[0];
    const float* n1w  = (const float*)d_in[1];
    const float* n1b  = (const float*)d_in[2];
    const float* qkvw = (const float*)d_in[3];
    const float* qkvb = (const float*)d_in[4];
    const float* rpb  = (const float*)d_in[5];
    const float* pw   = (const float*)d_in[6];
    const float* pb   = (const float*)d_in[7];
    const float* n2w  = (const float*)d_in[8];
    const float* n2b  = (const float*)d_in[9];
    const float* f1w  = (const float*)d_in[10];
    const float* f1b  = (const float*)d_in[11];
    const float* f2w  = (const float*)d_in[12];
    const float* f2b  = (const float*)d_in[13];
    float* out = (float*)d_out;

    cudaFuncSetAttribute(attn_kernel, cudaFuncAttributeMaxDynamicSharedMemorySize, ATTN_SMEM);

    prep_all<<<PREP_BIAS_BLOCKS + 144, BSTR>>>(rpb, qkvw, pw, f1w, f2w);
    ln1_kernel<<<MTOT / 8, 256>>>(x, n1w, n1b);
    hgemm_kernel<EPI_QKV, 96, 288><<<dim3(686, 3), 256>>>(qkvb, nullptr, nullptr, nullptr, nullptr);
    attn_kernel<<<NWINS * NHEAD, ATT_THR, ATTN_SMEM>>>();
    hgemm_kernel<EPI_PROJ, 96, 96><<<dim3(686, 1), 256>>>(pb, x, nullptr, n2w, n2b);
    hgemm_kernel<EPI_GELU, 96, 384><<<dim3(686, 4), 256>>>(f1b, nullptr, nullptr, nullptr, nullptr);
    hgemm_kernel<EPI_FC2, 384, 96><<<dim3(686, 1), 256>>>(f2b, nullptr, out, nullptr, nullptr);
}